// round 1
// baseline (speedup 1.0000x reference)
#include <cuda_runtime.h>
#include <cfloat>

// Problem constants
#define MROWS 32768      // B*T = 16*2048
#define INDIM 768
#define ENC   512
#define CDIM  128
#define NCODE 1024
#define NCB   8
#define ARGMIN_BLOCKS (MROWS / 64)   // 512

// ---------------- scratch (static device globals; no allocations) ----------------
__device__ float g_res[MROWS * ENC];      // running residual (64 MB)
__device__ float g_ze [MROWS * CDIM];     // z_e for current codebook (16 MB)
__device__ int   g_idx[MROWS];            // argmin codes for current codebook
__device__ float g_cnorm[NCB * NCODE];    // |c|^2 per codebook entry
__device__ float g_losspart[NCB * ARGMIN_BLOCKS];

// ---------------- codebook norms ----------------
__global__ void cnorm_kernel(const float* __restrict__ cbs) {
    int c = blockIdx.x * blockDim.x + threadIdx.x;   // 0..8191
    const float4* p = (const float4*)(cbs + (long)c * CDIM);
    float s = 0.f;
#pragma unroll
    for (int k = 0; k < CDIM / 4; k++) {
        float4 v = p[k];
        s += v.x * v.x + v.y * v.y + v.z * v.z + v.w * v.w;
    }
    g_cnorm[c] = s;
}

// ---------------- generic 128x128x16 fp32 GEMM ----------------
// C[M,N] (+=/-=) A[M,K] @ B[K,N]; optional bias add; optional gather of A rows
// through g_idx (A then points at the codebook base, K=CDIM).
// Requires M%128==0, N%128==0, K%16==0 (all shapes here satisfy this).
template <bool GATHER, bool BIAS, bool UPDATE>
__global__ void __launch_bounds__(256) sgemm128(
    const float* __restrict__ A, const float* __restrict__ B,
    const float* __restrict__ bias, float* __restrict__ C, int N, int K)
{
    __shared__ float As[16][132];   // [k][m], padded
    __shared__ float Bs[16][132];   // [k][n], padded

    const int tid = threadIdx.x;
    const int tx = tid & 15, ty = tid >> 4;
    const int rowBase = blockIdx.y * 128;
    const int colBase = blockIdx.x * 128;

    // A-load mapping: 2 float4 per thread
    const int aRow0 = tid >> 2;           // 0..63
    const int aK    = (tid & 3) << 2;     // 0,4,8,12
    // B-load mapping: 2 float4 per thread
    const int bRow0 = tid >> 5;           // 0..7
    const int bCol  = (tid & 31) << 2;    // 0..124

    const float* aPtr0;
    const float* aPtr1;
    if (GATHER) {
        aPtr0 = A + (long)g_idx[rowBase + aRow0] * K;
        aPtr1 = A + (long)g_idx[rowBase + aRow0 + 64] * K;
    } else {
        aPtr0 = A + (long)(rowBase + aRow0) * K;
        aPtr1 = A + (long)(rowBase + aRow0 + 64) * K;
    }
    const float* bPtr = B + colBase;

    float acc[8][8];
#pragma unroll
    for (int i = 0; i < 8; i++)
#pragma unroll
        for (int j = 0; j < 8; j++) acc[i][j] = 0.f;

    for (int kt = 0; kt < K; kt += 16) {
        float4 a0 = *(const float4*)(aPtr0 + kt + aK);
        float4 a1 = *(const float4*)(aPtr1 + kt + aK);
        float4 b0 = *(const float4*)(bPtr + (long)(kt + bRow0) * N + bCol);
        float4 b1 = *(const float4*)(bPtr + (long)(kt + bRow0 + 8) * N + bCol);

        As[aK + 0][aRow0] = a0.x; As[aK + 1][aRow0] = a0.y;
        As[aK + 2][aRow0] = a0.z; As[aK + 3][aRow0] = a0.w;
        As[aK + 0][aRow0 + 64] = a1.x; As[aK + 1][aRow0 + 64] = a1.y;
        As[aK + 2][aRow0 + 64] = a1.z; As[aK + 3][aRow0 + 64] = a1.w;
        *(float4*)&Bs[bRow0][bCol]     = b0;
        *(float4*)&Bs[bRow0 + 8][bCol] = b1;
        __syncthreads();

#pragma unroll
        for (int k = 0; k < 16; k++) {
            float4 af0 = *(const float4*)&As[k][ty * 8];
            float4 af1 = *(const float4*)&As[k][ty * 8 + 4];
            float4 bf0 = *(const float4*)&Bs[k][tx * 8];
            float4 bf1 = *(const float4*)&Bs[k][tx * 8 + 4];
            float ar[8] = {af0.x, af0.y, af0.z, af0.w, af1.x, af1.y, af1.z, af1.w};
            float br[8] = {bf0.x, bf0.y, bf0.z, bf0.w, bf1.x, bf1.y, bf1.z, bf1.w};
#pragma unroll
            for (int i = 0; i < 8; i++)
#pragma unroll
                for (int j = 0; j < 8; j++)
                    acc[i][j] += ar[i] * br[j];
        }
        __syncthreads();
    }

    float bb[8];
    if (BIAS) {
#pragma unroll
        for (int j = 0; j < 8; j++) bb[j] = bias[colBase + tx * 8 + j];
    }
#pragma unroll
    for (int i = 0; i < 8; i++) {
        long row = rowBase + ty * 8 + i;
        float* cp = C + row * N + colBase + tx * 8;
        if (UPDATE) {
            float4 c0 = *(float4*)cp;
            float4 c1 = *(float4*)(cp + 4);
            c0.x -= acc[i][0]; c0.y -= acc[i][1]; c0.z -= acc[i][2]; c0.w -= acc[i][3];
            c1.x -= acc[i][4]; c1.y -= acc[i][5]; c1.z -= acc[i][6]; c1.w -= acc[i][7];
            *(float4*)cp = c0; *(float4*)(cp + 4) = c1;
        } else {
            float4 o0 = make_float4(acc[i][0], acc[i][1], acc[i][2], acc[i][3]);
            float4 o1 = make_float4(acc[i][4], acc[i][5], acc[i][6], acc[i][7]);
            if (BIAS) {
                o0.x += bb[0]; o0.y += bb[1]; o0.z += bb[2]; o0.w += bb[3];
                o1.x += bb[4]; o1.y += bb[5]; o1.z += bb[6]; o1.w += bb[7];
            }
            *(float4*)cp = o0; *(float4*)(cp + 4) = o1;
        }
    }
}

// ---------------- fused distance / argmin / loss ----------------
// Per block: 64 rows, all 1024 codes (8 tiles of 128). score = |c|^2 - 2*ze.c
// (the |ze|^2 row constant is added back only for the loss term).
// Thread layout: 256 threads = 8 warps; warp w owns rows w*8..w*8+7,
// lane ci owns codes {tile*128 + ci*4 .. +3}.
__global__ void __launch_bounds__(256) argmin_kernel(
    const float* __restrict__ ze, const float* __restrict__ cb,
    float* __restrict__ codesOut, int cbIndex)
{
    extern __shared__ float smem[];
    float* zeS = smem;                   // 64*128
    float* cbS = smem + 64 * 128;        // 128*128, [k][code]
    float* cnS = cbS + 128 * 128;        // 128
    float* wsum = cnS + 128;             // 8

    const int tid = threadIdx.x;
    const int rowBase = blockIdx.x * 64;

    {   // stage z_e rows
        const float4* src = (const float4*)(ze + (long)rowBase * CDIM);
        float4* dst = (float4*)zeS;
        for (int i = tid; i < 64 * CDIM / 4; i += 256) dst[i] = src[i];
    }

    const int ri = tid >> 5, ci = tid & 31;
    float best[8]; int bidx[8];
#pragma unroll
    for (int r = 0; r < 8; r++) { best[r] = FLT_MAX; bidx[r] = 0; }

    for (int t = 0; t < 8; t++) {
        __syncthreads();   // protects cbS reuse + first-iter zeS visibility
        {   // load codebook tile transposed into cbS[k][code]
            const float4* src = (const float4*)(cb + (long)t * 128 * CDIM);
            for (int j = tid; j < 128 * (CDIM / 4); j += 256) {
                float4 v = src[j];
                int code = j >> 5;
                int k = (j & 31) << 2;
                cbS[(k + 0) * 128 + code] = v.x;
                cbS[(k + 1) * 128 + code] = v.y;
                cbS[(k + 2) * 128 + code] = v.z;
                cbS[(k + 3) * 128 + code] = v.w;
            }
            if (tid < 128) cnS[tid] = g_cnorm[cbIndex * NCODE + t * 128 + tid];
        }
        __syncthreads();

        float acc[8][4];
#pragma unroll
        for (int r = 0; r < 8; r++)
#pragma unroll
            for (int c = 0; c < 4; c++) acc[r][c] = 0.f;

#pragma unroll 2
        for (int k4 = 0; k4 < CDIM / 4; k4++) {
            float4 b0 = ((const float4*)(cbS + (k4 * 4 + 0) * 128))[ci];
            float4 b1 = ((const float4*)(cbS + (k4 * 4 + 1) * 128))[ci];
            float4 b2 = ((const float4*)(cbS + (k4 * 4 + 2) * 128))[ci];
            float4 b3 = ((const float4*)(cbS + (k4 * 4 + 3) * 128))[ci];
#pragma unroll
            for (int r = 0; r < 8; r++) {
                float4 a = ((const float4*)(zeS + (ri * 8 + r) * CDIM))[k4];
                acc[r][0] += a.x * b0.x + a.y * b1.x + a.z * b2.x + a.w * b3.x;
                acc[r][1] += a.x * b0.y + a.y * b1.y + a.z * b2.y + a.w * b3.y;
                acc[r][2] += a.x * b0.z + a.y * b1.z + a.z * b2.z + a.w * b3.z;
                acc[r][3] += a.x * b0.w + a.y * b1.w + a.z * b2.w + a.w * b3.w;
            }
        }

        float4 cn = ((const float4*)cnS)[ci];
        const int base = t * 128 + ci * 4;
#pragma unroll
        for (int r = 0; r < 8; r++) {
            float s0 = cn.x - 2.f * acc[r][0];
            float s1 = cn.y - 2.f * acc[r][1];
            float s2 = cn.z - 2.f * acc[r][2];
            float s3 = cn.w - 2.f * acc[r][3];
            if (s0 < best[r]) { best[r] = s0; bidx[r] = base + 0; }
            if (s1 < best[r]) { best[r] = s1; bidx[r] = base + 1; }
            if (s2 < best[r]) { best[r] = s2; bidx[r] = base + 2; }
            if (s3 < best[r]) { best[r] = s3; bidx[r] = base + 3; }
        }
    }

    // warp-level reduce: argmin (first-index tie-break) + row-norm sum
    float myloss = 0.f;
#pragma unroll
    for (int r = 0; r < 8; r++) {
        int row = ri * 8 + r;
        float4 zv = ((const float4*)(zeS + row * CDIM))[ci];
        float nrm = zv.x * zv.x + zv.y * zv.y + zv.z * zv.z + zv.w * zv.w;
        float bv = best[r]; int bi = bidx[r];
#pragma unroll
        for (int off = 16; off; off >>= 1) {
            float ov = __shfl_down_sync(0xffffffffu, bv, off);
            int   oi = __shfl_down_sync(0xffffffffu, bi, off);
            nrm += __shfl_down_sync(0xffffffffu, nrm, off);
            if (ov < bv || (ov == bv && oi < bi)) { bv = ov; bi = oi; }
        }
        if (ci == 0) {
            int grow = rowBase + row;
            g_idx[grow] = bi;
            codesOut[(long)grow * NCB + cbIndex] = (float)bi;
            myloss += nrm + bv;     // = sum_k (z_e - z_q)^2 for this row
        }
    }
    if (ci == 0) wsum[ri] = myloss;
    __syncthreads();
    if (tid == 0) {
        float s = 0.f;
        for (int w = 0; w < 8; w++) s += wsum[w];
        g_losspart[cbIndex * ARGMIN_BLOCKS + blockIdx.x] = s;
    }
}

// ---------------- deterministic loss finalize ----------------
__global__ void finalize_kernel(float* __restrict__ out) {
    __shared__ float s[256];
    float v = 0.f;
    for (int i = threadIdx.x; i < NCB * ARGMIN_BLOCKS; i += 256) v += g_losspart[i];
    s[threadIdx.x] = v;
    __syncthreads();
    for (int o = 128; o; o >>= 1) {
        if (threadIdx.x < o) s[threadIdx.x] += s[threadIdx.x + o];
        __syncthreads();
    }
    if (threadIdx.x == 0)
        out[(long)MROWS * NCB] = s[0] * 1.25f / ((float)MROWS * (float)CDIM);
}

// ---------------- launch ----------------
extern "C" void kernel_launch(void* const* d_in, const int* in_sizes, int n_in,
                              void* d_out, int out_size) {
    const float* z     = (const float*)d_in[0];
    const float* W_in  = (const float*)d_in[1];
    const float* b_in  = (const float*)d_in[2];
    const float* cbs   = (const float*)d_in[3];
    const float* in_w  = (const float*)d_in[4];
    const float* out_w = (const float*)d_in[5];
    float* out = (float*)d_out;

    float *res, *ze;
    cudaGetSymbolAddress((void**)&res, g_res);
    cudaGetSymbolAddress((void**)&ze,  g_ze);

    const int smemBytes = (64 * 128 + 128 * 128 + 128 + 8) * (int)sizeof(float);
    cudaFuncSetAttribute(argmin_kernel,
                         cudaFuncAttributeMaxDynamicSharedMemorySize, smemBytes);

    // |c|^2 for all codebooks
    cnorm_kernel<<<NCB * NCODE / 256, 256>>>(cbs);

    // residual = z @ W_in + b_in
    sgemm128<false, true, false><<<dim3(ENC / 128, MROWS / 128), 256>>>(
        z, W_in, b_in, res, ENC, INDIM);

    for (int c = 0; c < NCB; c++) {
        // z_e = residual @ in_w[c]
        sgemm128<false, false, false><<<dim3(CDIM / 128, MROWS / 128), 256>>>(
            res, in_w + (long)c * ENC * CDIM, nullptr, ze, CDIM, ENC);
        // codes + loss
        argmin_kernel<<<ARGMIN_BLOCKS, 256, smemBytes>>>(
            ze, cbs + (long)c * NCODE * CDIM, out, c);
        // residual -= codebook[idx] @ out_w[c]   (gather fused into GEMM)
        sgemm128<true, false, true><<<dim3(ENC / 128, MROWS / 128), 256>>>(
            cbs + (long)c * NCODE * CDIM, out_w + (long)c * CDIM * ENC,
            nullptr, res, ENC, CDIM);
    }

    finalize_kernel<<<1, 256>>>(out);
}

// round 2
// speedup vs baseline: 1.5710x; 1.5710x over previous
#include <cuda_runtime.h>
#include <cfloat>

// Problem constants
#define MROWS 32768      // B*T = 16*2048
#define INDIM 768
#define ENC   512
#define CDIM  128
#define NCODE 1024
#define NCB   8
#define ABLOCKS (MROWS / 128)   // 256 argmin blocks

// ---------------- scratch (static device globals; no allocations) ----------------
__device__ float g_res[MROWS * ENC];      // running residual
__device__ float g_ze [MROWS * CDIM];     // z_e for current codebook
__device__ float g_rnorm[MROWS];          // |z_e|^2 per row (from ze-GEMM epilogue)
__device__ int   g_idx[MROWS];            // argmin codes for current codebook
__device__ float g_cnorm[NCB * NCODE];    // |c|^2 per codebook entry
__device__ float g_losspart[NCB * ABLOCKS];

// ---------------- codebook norms ----------------
__global__ void cnorm_kernel(const float* __restrict__ cbs) {
    int c = blockIdx.x * blockDim.x + threadIdx.x;   // 0..8191
    const float4* p = (const float4*)(cbs + (long)c * CDIM);
    float s = 0.f;
#pragma unroll
    for (int k = 0; k < CDIM / 4; k++) {
        float4 v = p[k];
        s += v.x * v.x + v.y * v.y + v.z * v.z + v.w * v.w;
    }
    g_cnorm[c] = s;
}

// ---------------- generic 128x128x16 fp32 GEMM, prefetch-pipelined ----------------
// C[M,N] (+=/-=) A[M,K] @ B[K,N]; optional bias; optional gather of A rows
// through g_idx; optional per-row norm of C written to g_rnorm (requires N==128,
// single col-tile). All shapes here satisfy M%128==0, N%128==0, K%16==0.
template <bool GATHER, bool BIAS, bool UPDATE, bool RNORM>
__global__ void __launch_bounds__(256, 2) sgemm128(
    const float* __restrict__ A, const float* __restrict__ B,
    const float* __restrict__ bias, float* __restrict__ C, int N, int K)
{
    __shared__ float As[16][132];   // [k][m], padded
    __shared__ float Bs[16][132];   // [k][n], padded

    const int tid = threadIdx.x;
    const int tx = tid & 15, ty = tid >> 4;
    const int rowBase = blockIdx.y * 128;
    const int colBase = blockIdx.x * 128;

    const int aRow0 = tid >> 2;           // 0..63
    const int aK    = (tid & 3) << 2;     // 0,4,8,12
    const int bRow0 = tid >> 5;           // 0..7
    const int bCol  = (tid & 31) << 2;    // 0..124

    const float* aPtr0;
    const float* aPtr1;
    if (GATHER) {
        aPtr0 = A + (long)g_idx[rowBase + aRow0] * K;
        aPtr1 = A + (long)g_idx[rowBase + aRow0 + 64] * K;
    } else {
        aPtr0 = A + (long)(rowBase + aRow0) * K;
        aPtr1 = A + (long)(rowBase + aRow0 + 64) * K;
    }
    const float* bPtr = B + colBase;

    float acc[8][8];
#pragma unroll
    for (int i = 0; i < 8; i++)
#pragma unroll
        for (int j = 0; j < 8; j++) acc[i][j] = 0.f;

    // prefetch k-chunk 0
    float4 a0 = *(const float4*)(aPtr0 + aK);
    float4 a1 = *(const float4*)(aPtr1 + aK);
    float4 b0 = *(const float4*)(bPtr + (long)bRow0 * N + bCol);
    float4 b1 = *(const float4*)(bPtr + (long)(bRow0 + 8) * N + bCol);

    for (int kt = 0; kt < K; kt += 16) {
        __syncthreads();
        As[aK + 0][aRow0] = a0.x; As[aK + 1][aRow0] = a0.y;
        As[aK + 2][aRow0] = a0.z; As[aK + 3][aRow0] = a0.w;
        As[aK + 0][aRow0 + 64] = a1.x; As[aK + 1][aRow0 + 64] = a1.y;
        As[aK + 2][aRow0 + 64] = a1.z; As[aK + 3][aRow0 + 64] = a1.w;
        *(float4*)&Bs[bRow0][bCol]     = b0;
        *(float4*)&Bs[bRow0 + 8][bCol] = b1;
        __syncthreads();

        if (kt + 16 < K) {   // prefetch next chunk; latency hidden by compute
            a0 = *(const float4*)(aPtr0 + kt + 16 + aK);
            a1 = *(const float4*)(aPtr1 + kt + 16 + aK);
            b0 = *(const float4*)(bPtr + (long)(kt + 16 + bRow0) * N + bCol);
            b1 = *(const float4*)(bPtr + (long)(kt + 16 + bRow0 + 8) * N + bCol);
        }

#pragma unroll
        for (int k = 0; k < 16; k++) {
            float4 af0 = *(const float4*)&As[k][ty * 8];
            float4 af1 = *(const float4*)&As[k][ty * 8 + 4];
            float4 bf0 = *(const float4*)&Bs[k][tx * 8];
            float4 bf1 = *(const float4*)&Bs[k][tx * 8 + 4];
            float ar[8] = {af0.x, af0.y, af0.z, af0.w, af1.x, af1.y, af1.z, af1.w};
            float br[8] = {bf0.x, bf0.y, bf0.z, bf0.w, bf1.x, bf1.y, bf1.z, bf1.w};
#pragma unroll
            for (int i = 0; i < 8; i++)
#pragma unroll
                for (int j = 0; j < 8; j++)
                    acc[i][j] += ar[i] * br[j];
        }
    }

    float bb[8];
    if (BIAS) {
#pragma unroll
        for (int j = 0; j < 8; j++) bb[j] = bias[colBase + tx * 8 + j];
    }
#pragma unroll
    for (int i = 0; i < 8; i++) {
        long row = rowBase + ty * 8 + i;
        float* cp = C + row * N + colBase + tx * 8;
        if (UPDATE) {
            float4 c0 = *(float4*)cp;
            float4 c1 = *(float4*)(cp + 4);
            c0.x -= acc[i][0]; c0.y -= acc[i][1]; c0.z -= acc[i][2]; c0.w -= acc[i][3];
            c1.x -= acc[i][4]; c1.y -= acc[i][5]; c1.z -= acc[i][6]; c1.w -= acc[i][7];
            *(float4*)cp = c0; *(float4*)(cp + 4) = c1;
        } else {
            float4 o0 = make_float4(acc[i][0], acc[i][1], acc[i][2], acc[i][3]);
            float4 o1 = make_float4(acc[i][4], acc[i][5], acc[i][6], acc[i][7]);
            if (BIAS) {
                o0.x += bb[0]; o0.y += bb[1]; o0.z += bb[2]; o0.w += bb[3];
                o1.x += bb[4]; o1.y += bb[5]; o1.z += bb[6]; o1.w += bb[7];
            }
            *(float4*)cp = o0; *(float4*)(cp + 4) = o1;
        }
    }

    if (RNORM) {   // per-row |C|^2 (N==128 single tile); width-16 shuffle reduce
#pragma unroll
        for (int i = 0; i < 8; i++) {
            float rn = 0.f;
#pragma unroll
            for (int j = 0; j < 8; j++) rn += acc[i][j] * acc[i][j];
#pragma unroll
            for (int off = 8; off; off >>= 1)
                rn += __shfl_down_sync(0xffffffffu, rn, off, 16);
            if (tx == 0) g_rnorm[rowBase + ty * 8 + i] = rn;
        }
    }
}

// ---------------- fused distance / argmin / loss, GEMM-style ----------------
// Block: 128 rows; loops over 8 code tiles of 128. scores = |c|^2 - 2 * ze.cb
// computed with the same 8x8 register micro-tile as sgemm128, then per-tile
// argmin update in registers; final width-16 shuffle reduce with first-index
// tie-break (matches jnp.argmin semantics).
__global__ void __launch_bounds__(256, 2) argmin_kernel(
    const float* __restrict__ ze, const float* __restrict__ cb,
    float* __restrict__ codesOut, int cbIndex)
{
    __shared__ float As[16][132];   // z_e^T chunk   [k][row]
    __shared__ float Bs[16][132];   // cb^T chunk    [k][code]
    __shared__ float ls[16];

    const int tid = threadIdx.x;
    const int tx = tid & 15, ty = tid >> 4;
    const int rowBase = blockIdx.x * 128;

    const int r0 = tid >> 2;            // 0..63 (row / code within tile)
    const int k0 = (tid & 3) << 2;      // 0,4,8,12

    const float* aPtr0 = ze + (long)(rowBase + r0) * CDIM;
    const float* aPtr1 = ze + (long)(rowBase + r0 + 64) * CDIM;

    float best[8]; int bidx[8];
#pragma unroll
    for (int i = 0; i < 8; i++) { best[i] = FLT_MAX; bidx[i] = 0; }

    float acc[8][8];

    // prefetch stage 0 (tile 0, kt 0)
    float4 a0 = *(const float4*)(aPtr0 + k0);
    float4 a1 = *(const float4*)(aPtr1 + k0);
    float4 b0 = *(const float4*)(cb + (long)r0 * CDIM + k0);
    float4 b1 = *(const float4*)(cb + (long)(r0 + 64) * CDIM + k0);

    for (int s = 0; s < 64; s++) {               // 8 tiles x 8 k-chunks
        const int kt = (s & 7) << 4;
        if (kt == 0) {
#pragma unroll
            for (int i = 0; i < 8; i++)
#pragma unroll
                for (int j = 0; j < 8; j++) acc[i][j] = 0.f;
        }

        __syncthreads();
        As[k0 + 0][r0] = a0.x; As[k0 + 1][r0] = a0.y;
        As[k0 + 2][r0] = a0.z; As[k0 + 3][r0] = a0.w;
        As[k0 + 0][r0 + 64] = a1.x; As[k0 + 1][r0 + 64] = a1.y;
        As[k0 + 2][r0 + 64] = a1.z; As[k0 + 3][r0 + 64] = a1.w;
        Bs[k0 + 0][r0] = b0.x; Bs[k0 + 1][r0] = b0.y;
        Bs[k0 + 2][r0] = b0.z; Bs[k0 + 3][r0] = b0.w;
        Bs[k0 + 0][r0 + 64] = b1.x; Bs[k0 + 1][r0 + 64] = b1.y;
        Bs[k0 + 2][r0 + 64] = b1.z; Bs[k0 + 3][r0 + 64] = b1.w;
        __syncthreads();

        if (s + 1 < 64) {   // prefetch next stage
            const int nt  = (s + 1) >> 3;
            const int nkt = ((s + 1) & 7) << 4;
            a0 = *(const float4*)(aPtr0 + nkt + k0);
            a1 = *(const float4*)(aPtr1 + nkt + k0);
            const float* cp = cb + (long)(nt * 128) * CDIM;
            b0 = *(const float4*)(cp + (long)r0 * CDIM + nkt + k0);
            b1 = *(const float4*)(cp + (long)(r0 + 64) * CDIM + nkt + k0);
        }

#pragma unroll
        for (int k = 0; k < 16; k++) {
            float4 af0 = *(const float4*)&As[k][ty * 8];
            float4 af1 = *(const float4*)&As[k][ty * 8 + 4];
            float4 bf0 = *(const float4*)&Bs[k][tx * 8];
            float4 bf1 = *(const float4*)&Bs[k][tx * 8 + 4];
            float ar[8] = {af0.x, af0.y, af0.z, af0.w, af1.x, af1.y, af1.z, af1.w};
            float br[8] = {bf0.x, bf0.y, bf0.z, bf0.w, bf1.x, bf1.y, bf1.z, bf1.w};
#pragma unroll
            for (int i = 0; i < 8; i++)
#pragma unroll
                for (int j = 0; j < 8; j++)
                    acc[i][j] += ar[i] * br[j];
        }

        if ((s & 7) == 7) {   // tile complete: score + argmin update
            const int t = s >> 3;
            const float* cnp = g_cnorm + cbIndex * NCODE + t * 128 + tx * 8;
            float4 cn0 = *(const float4*)cnp;
            float4 cn1 = *(const float4*)(cnp + 4);
            float cn[8] = {cn0.x, cn0.y, cn0.z, cn0.w, cn1.x, cn1.y, cn1.z, cn1.w};
            const int base = t * 128 + tx * 8;
#pragma unroll
            for (int i = 0; i < 8; i++) {
#pragma unroll
                for (int j = 0; j < 8; j++) {
                    float sc = cn[j] - 2.f * acc[i][j];
                    if (sc < best[i]) { best[i] = sc; bidx[i] = base + j; }
                }
            }
        }
    }

    // cross-thread reduce over tx (width 16), first-index tie-break
    float lossAcc = 0.f;
#pragma unroll
    for (int i = 0; i < 8; i++) {
        float bv = best[i]; int bi = bidx[i];
#pragma unroll
        for (int off = 8; off; off >>= 1) {
            float ov = __shfl_down_sync(0xffffffffu, bv, off, 16);
            int   oi = __shfl_down_sync(0xffffffffu, bi, off, 16);
            if (ov < bv || (ov == bv && oi < bi)) { bv = ov; bi = oi; }
        }
        if (tx == 0) {
            int row = rowBase + ty * 8 + i;
            g_idx[row] = bi;
            codesOut[(long)row * NCB + cbIndex] = (float)bi;
            lossAcc += g_rnorm[row] + bv;   // = sum_k (z_e - z_q)^2
        }
    }
    if (tx == 0) ls[ty] = lossAcc;
    __syncthreads();
    if (tid == 0) {
        float sum = 0.f;
        for (int w = 0; w < 16; w++) sum += ls[w];
        g_losspart[cbIndex * ABLOCKS + blockIdx.x] = sum;
    }
}

// ---------------- deterministic loss finalize (double accumulation) ----------------
__global__ void finalize_kernel(float* __restrict__ out) {
    __shared__ double s[256];
    double v = 0.0;
    for (int i = threadIdx.x; i < NCB * ABLOCKS; i += 256) v += (double)g_losspart[i];
    s[threadIdx.x] = v;
    __syncthreads();
    for (int o = 128; o; o >>= 1) {
        if (threadIdx.x < o) s[threadIdx.x] += s[threadIdx.x + o];
        __syncthreads();
    }
    if (threadIdx.x == 0)
        out[(long)MROWS * NCB] =
            (float)(s[0] * 1.25 / ((double)MROWS * (double)CDIM));
}

// ---------------- launch ----------------
extern "C" void kernel_launch(void* const* d_in, const int* in_sizes, int n_in,
                              void* d_out, int out_size) {
    const float* z     = (const float*)d_in[0];
    const float* W_in  = (const float*)d_in[1];
    const float* b_in  = (const float*)d_in[2];
    const float* cbs   = (const float*)d_in[3];
    const float* in_w  = (const float*)d_in[4];
    const float* out_w = (const float*)d_in[5];
    float* out = (float*)d_out;

    float *res, *ze;
    cudaGetSymbolAddress((void**)&res, g_res);
    cudaGetSymbolAddress((void**)&ze,  g_ze);

    // |c|^2 for all codebooks
    cnorm_kernel<<<NCB * NCODE / 256, 256>>>(cbs);

    // residual = z @ W_in + b_in
    sgemm128<false, true, false, false><<<dim3(ENC / 128, MROWS / 128), 256>>>(
        z, W_in, b_in, res, ENC, INDIM);

    for (int c = 0; c < NCB; c++) {
        // z_e = residual @ in_w[c]; fused |z_e|^2 row norms
        sgemm128<false, false, false, true><<<dim3(CDIM / 128, MROWS / 128), 256>>>(
            res, in_w + (long)c * ENC * CDIM, nullptr, ze, CDIM, ENC);
        // codes + loss
        argmin_kernel<<<ABLOCKS, 256>>>(
            ze, cbs + (long)c * NCODE * CDIM, out, c);
        // residual -= codebook[idx] @ out_w[c]   (gather fused into GEMM)
        sgemm128<true, false, true, false><<<dim3(ENC / 128, MROWS / 128), 256>>>(
            cbs + (long)c * NCODE * CDIM, out_w + (long)c * CDIM * ENC,
            nullptr, res, ENC, CDIM);
    }

    finalize_kernel<<<1, 256>>>(out);
}

// round 3
// speedup vs baseline: 1.6734x; 1.0652x over previous
#include <cuda_runtime.h>
#include <cfloat>

// Problem constants
#define MROWS 32768      // B*T = 16*2048
#define INDIM 768
#define ENC   512
#define CDIM  128
#define NCODE 1024
#define NCB   8
#define ABLOCKS (MROWS / 128)   // 256 row-tile blocks

#define ZP 132           // smem row stride (floats), 16B-aligned

// ---------------- scratch (static device globals; no allocations) ----------------
__device__ float g_res[MROWS * ENC];      // running residual
__device__ int   g_idx[MROWS];            // argmin codes for current codebook
__device__ float g_cnorm[NCB * NCODE];    // |c|^2 per codebook entry
__device__ float g_losspart[NCB * ABLOCKS];

// ---------------- codebook norms ----------------
__global__ void cnorm_kernel(const float* __restrict__ cbs) {
    int c = blockIdx.x * blockDim.x + threadIdx.x;   // 0..8191
    const float4* p = (const float4*)(cbs + (long)c * CDIM);
    float s = 0.f;
#pragma unroll
    for (int k = 0; k < CDIM / 4; k++) {
        float4 v = p[k];
        s += v.x * v.x + v.y * v.y + v.z * v.z + v.w * v.w;
    }
    g_cnorm[c] = s;
}

// ---------------- shared micro-kernel pieces ----------------
// 16-k FMA block; As/Bs have row stride ZP; per-thread 8x8 tile, k-ascending
// accumulation (this exact order is load-bearing for bit-reproducibility).
__device__ __forceinline__ void mma16(const float* __restrict__ As,
                                      const float* __restrict__ Bs,
                                      float (&acc)[8][8], int tx, int ty) {
#pragma unroll
    for (int k = 0; k < 16; k++) {
        float4 af0 = *(const float4*)(As + k * ZP + ty * 8);
        float4 af1 = *(const float4*)(As + k * ZP + ty * 8 + 4);
        float4 bf0 = *(const float4*)(Bs + k * ZP + tx * 8);
        float4 bf1 = *(const float4*)(Bs + k * ZP + tx * 8 + 4);
        float ar[8] = {af0.x, af0.y, af0.z, af0.w, af1.x, af1.y, af1.z, af1.w};
        float br[8] = {bf0.x, bf0.y, bf0.z, bf0.w, bf1.x, bf1.y, bf1.z, bf1.w};
#pragma unroll
        for (int i = 0; i < 8; i++)
#pragma unroll
            for (int j = 0; j < 8; j++)
                acc[i][j] += ar[i] * br[j];
    }
}

// transpose-stage two float4 (rows r0, r0+64; k-cols k0..k0+3) into S[k][row]
__device__ __forceinline__ void stageT(float* __restrict__ S, int r0, int k0,
                                       float4 a0, float4 a1) {
    S[(k0 + 0) * ZP + r0] = a0.x; S[(k0 + 1) * ZP + r0] = a0.y;
    S[(k0 + 2) * ZP + r0] = a0.z; S[(k0 + 3) * ZP + r0] = a0.w;
    S[(k0 + 0) * ZP + r0 + 64] = a1.x; S[(k0 + 1) * ZP + r0 + 64] = a1.y;
    S[(k0 + 2) * ZP + r0 + 64] = a1.z; S[(k0 + 3) * ZP + r0 + 64] = a1.w;
}

// ---------------- proj GEMM: res = z @ W_in + b_in ----------------
// 128x128 tile, double-buffered smem, one sync per k-chunk.
__global__ void __launch_bounds__(256, 2) proj_kernel(
    const float* __restrict__ A, const float* __restrict__ B,
    const float* __restrict__ bias, float* __restrict__ C)
{
    __shared__ float stA[2 * 16 * ZP];
    __shared__ float stB[2 * 16 * ZP];

    const int tid = threadIdx.x;
    const int tx = tid & 15, ty = tid >> 4;
    const int rowBase = blockIdx.y * 128;
    const int colBase = blockIdx.x * 128;
    const int r0 = tid >> 2, k0 = (tid & 3) << 2;
    const int bR = tid >> 5, bC = (tid & 31) << 2;

    const float* aP0 = A + (long)(rowBase + r0) * INDIM;
    const float* aP1 = A + (long)(rowBase + r0 + 64) * INDIM;
    const float* bP  = B + colBase;

    float acc[8][8];
#pragma unroll
    for (int i = 0; i < 8; i++)
#pragma unroll
        for (int j = 0; j < 8; j++) acc[i][j] = 0.f;

    float4 a0 = *(const float4*)(aP0 + k0);
    float4 a1 = *(const float4*)(aP1 + k0);
    float4 b0 = *(const float4*)(bP + (long)bR * ENC + bC);
    float4 b1 = *(const float4*)(bP + (long)(bR + 8) * ENC + bC);

    const int NCH = INDIM / 16;   // 48
    for (int s = 0; s < NCH; s++) {
        float* As = stA + (s & 1) * 16 * ZP;
        float* Bs = stB + (s & 1) * 16 * ZP;
        stageT(As, r0, k0, a0, a1);
        *(float4*)&Bs[bR * ZP + bC]       = b0;
        *(float4*)&Bs[(bR + 8) * ZP + bC] = b1;
        __syncthreads();
        if (s + 1 < NCH) {
            int nkt = (s + 1) * 16;
            a0 = *(const float4*)(aP0 + nkt + k0);
            a1 = *(const float4*)(aP1 + nkt + k0);
            b0 = *(const float4*)(bP + (long)(nkt + bR) * ENC + bC);
            b1 = *(const float4*)(bP + (long)(nkt + bR + 8) * ENC + bC);
        }
        mma16(As, Bs, acc, tx, ty);
    }

    float bb[8];
#pragma unroll
    for (int j = 0; j < 8; j++) bb[j] = bias[colBase + tx * 8 + j];
#pragma unroll
    for (int i = 0; i < 8; i++) {
        long row = rowBase + ty * 8 + i;
        float* cp = C + row * ENC + colBase + tx * 8;
        float4 o0 = make_float4(acc[i][0] + bb[0], acc[i][1] + bb[1],
                                acc[i][2] + bb[2], acc[i][3] + bb[3]);
        float4 o1 = make_float4(acc[i][4] + bb[4], acc[i][5] + bb[5],
                                acc[i][6] + bb[6], acc[i][7] + bb[7]);
        *(float4*)cp = o0; *(float4*)(cp + 4) = o1;
    }
}

// ---------------- fused per-codebook kernel ----------------
// phase 0 (cbIndex>0): res -= prevCb[g_idx] @ prevOutW   (4 col-passes, K=128)
// phase 1: z_e = res @ inW (K=512) -> kept in smem [k][row]; row norms
// phase 2: scores = |c|^2 - 2 * z_e.cb over 8 code tiles; argmin + loss
// All phase-0/1 FMA accumulation orders are identical to the previous separate
// kernels -> z_e chain is bit-exact across rounds.
__global__ void __launch_bounds__(256, 2) fused_kernel(
    float* __restrict__ res,
    const float* __restrict__ prevCb, const float* __restrict__ prevOutW,
    const float* __restrict__ inW, const float* __restrict__ cb,
    float* __restrict__ codesOut, int cbIndex)
{
    extern __shared__ float sm[];
    float* zeS = sm;                              // 128*ZP = 16896
    float* stA = sm + 128 * ZP;                   // 2*16*ZP = 4224
    float* stB = stA + 2 * 16 * ZP;               // 2*16*ZP = 4224
    float* rnS = stB + 2 * 16 * ZP;               // 128
    float* lsS = rnS + 128;                       // 16
    int*   idxS = (int*)(lsS + 16);               // 128

    const int tid = threadIdx.x;
    const int tx = tid & 15, ty = tid >> 4;
    const int rowBase = blockIdx.x * 128;
    const int r0 = tid >> 2, k0 = (tid & 3) << 2;
    const int bR = tid >> 5, bC = (tid & 31) << 2;

    float acc[8][8];

    // ================= phase 0: residual update =================
    if (cbIndex > 0) {
        if (tid < 128) idxS[tid] = g_idx[rowBase + tid];
        __syncthreads();
        const float* aP0 = prevCb + (long)idxS[r0] * CDIM;
        const float* aP1 = prevCb + (long)idxS[r0 + 64] * CDIM;

        float4 a0 = *(const float4*)(aP0 + k0);
        float4 a1 = *(const float4*)(aP1 + k0);
        float4 b0 = *(const float4*)(prevOutW + (long)bR * ENC + bC);
        float4 b1 = *(const float4*)(prevOutW + (long)(bR + 8) * ENC + bC);

        for (int s = 0; s < 32; s++) {            // 4 col-passes x 8 k-chunks
            float* As = stA + (s & 1) * 16 * ZP;
            float* Bs = stB + (s & 1) * 16 * ZP;
            stageT(As, r0, k0, a0, a1);
            *(float4*)&Bs[bR * ZP + bC]       = b0;
            *(float4*)&Bs[(bR + 8) * ZP + bC] = b1;
            __syncthreads();
            if (s + 1 < 32) {
                int np = (s + 1) >> 3, nkt = ((s + 1) & 7) << 4;
                a0 = *(const float4*)(aP0 + nkt + k0);
                a1 = *(const float4*)(aP1 + nkt + k0);
                const float* bp = prevOutW + np * 128;
                b0 = *(const float4*)(bp + (long)(nkt + bR) * ENC + bC);
                b1 = *(const float4*)(bp + (long)(nkt + bR + 8) * ENC + bC);
            }
            if ((s & 7) == 0) {
#pragma unroll
                for (int i = 0; i < 8; i++)
#pragma unroll
                    for (int j = 0; j < 8; j++) acc[i][j] = 0.f;
            }
            mma16(As, Bs, acc, tx, ty);
            if ((s & 7) == 7) {
                int colBase = (s >> 3) * 128;
#pragma unroll
                for (int i = 0; i < 8; i++) {
                    long row = rowBase + ty * 8 + i;
                    float* cp = res + row * ENC + colBase + tx * 8;
                    float4 c0 = *(float4*)cp;
                    float4 c1 = *(float4*)(cp + 4);
                    c0.x -= acc[i][0]; c0.y -= acc[i][1];
                    c0.z -= acc[i][2]; c0.w -= acc[i][3];
                    c1.x -= acc[i][4]; c1.y -= acc[i][5];
                    c1.z -= acc[i][6]; c1.w -= acc[i][7];
                    *(float4*)cp = c0; *(float4*)(cp + 4) = c1;
                }
            }
        }
        __syncthreads();   // res update visible block-wide before phase 1
    }

    // ================= phase 1: z_e GEMM (K=512) =================
    {
        const float* aP0 = res + (long)(rowBase + r0) * ENC;
        const float* aP1 = res + (long)(rowBase + r0 + 64) * ENC;

#pragma unroll
        for (int i = 0; i < 8; i++)
#pragma unroll
            for (int j = 0; j < 8; j++) acc[i][j] = 0.f;

        float4 a0 = *(const float4*)(aP0 + k0);
        float4 a1 = *(const float4*)(aP1 + k0);
        float4 b0 = *(const float4*)(inW + (long)bR * CDIM + bC);
        float4 b1 = *(const float4*)(inW + (long)(bR + 8) * CDIM + bC);

        for (int s = 0; s < 32; s++) {            // 32 k-chunks of 16
            float* As = stA + (s & 1) * 16 * ZP;
            float* Bs = stB + (s & 1) * 16 * ZP;
            stageT(As, r0, k0, a0, a1);
            *(float4*)&Bs[bR * ZP + bC]       = b0;
            *(float4*)&Bs[(bR + 8) * ZP + bC] = b1;
            __syncthreads();
            if (s + 1 < 32) {
                int nkt = (s + 1) * 16;
                a0 = *(const float4*)(aP0 + nkt + k0);
                a1 = *(const float4*)(aP1 + nkt + k0);
                b0 = *(const float4*)(inW + (long)(nkt + bR) * CDIM + bC);
                b1 = *(const float4*)(inW + (long)(nkt + bR + 8) * CDIM + bC);
            }
            mma16(As, Bs, acc, tx, ty);
        }

        // row norms |z_e|^2 (same order as R2's RNORM path)
#pragma unroll
        for (int i = 0; i < 8; i++) {
            float rn = 0.f;
#pragma unroll
            for (int j = 0; j < 8; j++) rn += acc[i][j] * acc[i][j];
#pragma unroll
            for (int off = 8; off; off >>= 1)
                rn += __shfl_down_sync(0xffffffffu, rn, off, 16);
            if (tx == 0) rnS[ty * 8 + i] = rn;
        }
        __syncthreads();   // staging buffers free before z_e transpose-store
        // z_e -> zeS[k][row] (one-time scatter)
#pragma unroll
        for (int i = 0; i < 8; i++)
#pragma unroll
            for (int j = 0; j < 8; j++)
                zeS[(tx * 8 + j) * ZP + ty * 8 + i] = acc[i][j];
        __syncthreads();
    }

    // ================= phase 2: distance / argmin / loss =================
    float best[8]; int bidx[8];
#pragma unroll
    for (int i = 0; i < 8; i++) { best[i] = FLT_MAX; bidx[i] = 0; }

    float4 b0 = *(const float4*)(cb + (long)r0 * CDIM + k0);
    float4 b1 = *(const float4*)(cb + (long)(r0 + 64) * CDIM + k0);

    for (int s = 0; s < 64; s++) {                // 8 code tiles x 8 k-chunks
        const int kt = (s & 7) << 4;
        float* Bs = ((s & 1) ? stB : stA);        // ping-pong across both buffers
        stageT(Bs, r0, k0, b0, b1);
        __syncthreads();
        if (s + 1 < 64) {
            int nt = (s + 1) >> 3, nkt = ((s + 1) & 7) << 4;
            const float* cp2 = cb + (long)(nt * 128) * CDIM;
            b0 = *(const float4*)(cp2 + (long)r0 * CDIM + nkt + k0);
            b1 = *(const float4*)(cp2 + (long)(r0 + 64) * CDIM + nkt + k0);
        }
        if (kt == 0) {
#pragma unroll
            for (int i = 0; i < 8; i++)
#pragma unroll
                for (int j = 0; j < 8; j++) acc[i][j] = 0.f;
        }
        mma16(zeS + kt * ZP, Bs, acc, tx, ty);
        if ((s & 7) == 7) {                        // tile complete
            const int t = s >> 3;
            const float* cnp = g_cnorm + cbIndex * NCODE + t * 128 + tx * 8;
            float4 cn0 = *(const float4*)cnp;
            float4 cn1 = *(const float4*)(cnp + 4);
            float cn[8] = {cn0.x, cn0.y, cn0.z, cn0.w, cn1.x, cn1.y, cn1.z, cn1.w};
            const int base = t * 128 + tx * 8;
#pragma unroll
            for (int i = 0; i < 8; i++) {
#pragma unroll
                for (int j = 0; j < 8; j++) {
                    float sc = cn[j] - 2.f * acc[i][j];
                    if (sc < best[i]) { best[i] = sc; bidx[i] = base + j; }
                }
            }
        }
    }

    // cross-thread reduce over tx (width 16), first-index tie-break
    float lossAcc = 0.f;
#pragma unroll
    for (int i = 0; i < 8; i++) {
        float bv = best[i]; int bi = bidx[i];
#pragma unroll
        for (int off = 8; off; off >>= 1) {
            float ov = __shfl_down_sync(0xffffffffu, bv, off, 16);
            int   oi = __shfl_down_sync(0xffffffffu, bi, off, 16);
            if (ov < bv || (ov == bv && oi < bi)) { bv = ov; bi = oi; }
        }
        if (tx == 0) {
            int row = rowBase + ty * 8 + i;
            g_idx[row] = bi;
            codesOut[(long)row * NCB + cbIndex] = (float)bi;
            lossAcc += rnS[ty * 8 + i] + bv;       // = sum_k (z_e - z_q)^2
        }
    }
    if (tx == 0) lsS[ty] = lossAcc;
    __syncthreads();
    if (tid == 0) {
        float sum = 0.f;
        for (int w = 0; w < 16; w++) sum += lsS[w];
        g_losspart[cbIndex * ABLOCKS + blockIdx.x] = sum;
    }
}

// ---------------- deterministic loss finalize (double accumulation) ----------------
__global__ void finalize_kernel(float* __restrict__ out) {
    __shared__ double s[256];
    double v = 0.0;
    for (int i = threadIdx.x; i < NCB * ABLOCKS; i += 256) v += (double)g_losspart[i];
    s[threadIdx.x] = v;
    __syncthreads();
    for (int o = 128; o; o >>= 1) {
        if (threadIdx.x < o) s[threadIdx.x] += s[threadIdx.x + o];
        __syncthreads();
    }
    if (threadIdx.x == 0)
        out[(long)MROWS * NCB] =
            (float)(s[0] * 1.25 / ((double)MROWS * (double)CDIM));
}

// ---------------- launch ----------------
extern "C" void kernel_launch(void* const* d_in, const int* in_sizes, int n_in,
                              void* d_out, int out_size) {
    const float* z     = (const float*)d_in[0];
    const float* W_in  = (const float*)d_in[1];
    const float* b_in  = (const float*)d_in[2];
    const float* cbs   = (const float*)d_in[3];
    const float* in_w  = (const float*)d_in[4];
    const float* out_w = (const float*)d_in[5];
    float* out = (float*)d_out;

    float* res;
    cudaGetSymbolAddress((void**)&res, g_res);

    const int fusedSmem = (128 * ZP + 4 * 16 * ZP + 128 + 16 + 128) * (int)sizeof(float);
    cudaFuncSetAttribute(fused_kernel,
                         cudaFuncAttributeMaxDynamicSharedMemorySize, fusedSmem);

    // |c|^2 for all codebooks
    cnorm_kernel<<<NCB * NCODE / 256, 256>>>(cbs);

    // res = z @ W_in + b_in
    proj_kernel<<<dim3(ENC / 128, MROWS / 128), 256>>>(z, W_in, b_in, res);

    for (int c = 0; c < NCB; c++) {
        fused_kernel<<<ABLOCKS, 256, fusedSmem>>>(
            res,
            c > 0 ? cbs + (long)(c - 1) * NCODE * CDIM : cbs,
            c > 0 ? out_w + (long)(c - 1) * CDIM * ENC : out_w,
            in_w + (long)c * ENC * CDIM,
            cbs + (long)c * NCODE * CDIM,
            out, c);
    }

    finalize_kernel<<<1, 256>>>(out);
}

// round 4
// speedup vs baseline: 1.7630x; 1.0535x over previous
#include <cuda_runtime.h>
#include <cfloat>

// Problem constants
#define MROWS 32768      // B*T = 16*2048
#define INDIM 768
#define ENC   512
#define CDIM  128
#define NCODE 1024
#define NCB   8
#define ABLOCKS (MROWS / 128)   // 256 row-tile blocks

#define ZP 132           // smem row stride (floats), 16B-aligned

// ---------------- scratch (static device globals; no allocations) ----------------
__device__ float g_res[MROWS * ENC];      // running residual
__device__ int   g_idx[MROWS];            // argmin codes for current codebook
__device__ float g_cnorm[NCB * NCODE];    // |c|^2 per codebook entry
__device__ float g_losspart[NCB * ABLOCKS];

// ---------------- packed f32x2 helpers (Blackwell sm_100+) ----------------
// fma.rn.f32x2: two independent fp32 RN FMAs per instruction — lane-wise
// bit-identical to scalar FFMA, 2x issue throughput.
__device__ __forceinline__ void ffma2(unsigned long long& d,
                                      unsigned long long a,
                                      unsigned long long b) {
    asm("fma.rn.f32x2 %0, %1, %2, %3;" : "=l"(d) : "l"(a), "l"(b), "l"(d));
}
__device__ __forceinline__ unsigned long long bcast2(float v) {
    unsigned long long r;
    asm("mov.b64 %0, {%1, %1};" : "=l"(r) : "f"(v));
    return r;
}
__device__ __forceinline__ float2 unpack2(unsigned long long v) {
    unsigned int lo, hi;
    asm("mov.b64 {%0, %1}, %2;" : "=r"(lo), "=r"(hi) : "l"(v));
    return make_float2(__uint_as_float(lo), __uint_as_float(hi));
}

// ---------------- codebook norms ----------------
__global__ void cnorm_kernel(const float* __restrict__ cbs) {
    int c = blockIdx.x * blockDim.x + threadIdx.x;   // 0..8191
    const float4* p = (const float4*)(cbs + (long)c * CDIM);
    float s = 0.f;
#pragma unroll
    for (int k = 0; k < CDIM / 4; k++) {
        float4 v = p[k];
        s += v.x * v.x + v.y * v.y + v.z * v.z + v.w * v.w;
    }
    g_cnorm[c] = s;
}

// ---------------- shared micro-kernel pieces ----------------
// 16-k packed-FMA block. acc[i][j2] holds columns {2*j2, 2*j2+1} of the 8x8
// per-thread tile as an f32x2 pair. Per-element accumulation is k-ascending
// RN fp32 — bit-identical to the scalar FFMA version.
__device__ __forceinline__ void mma16p(const float* __restrict__ As,
                                       const float* __restrict__ Bs,
                                       unsigned long long (&acc)[8][4],
                                       int tx, int ty) {
#pragma unroll
    for (int k = 0; k < 16; k++) {
        float4 af0 = *(const float4*)(As + k * ZP + ty * 8);
        float4 af1 = *(const float4*)(As + k * ZP + ty * 8 + 4);
        ulonglong2 bv0 = *(const ulonglong2*)(Bs + k * ZP + tx * 8);
        ulonglong2 bv1 = *(const ulonglong2*)(Bs + k * ZP + tx * 8 + 4);
        unsigned long long bp[4] = {bv0.x, bv0.y, bv1.x, bv1.y};
        float ar[8] = {af0.x, af0.y, af0.z, af0.w, af1.x, af1.y, af1.z, af1.w};
        unsigned long long ap[8];
#pragma unroll
        for (int i = 0; i < 8; i++) ap[i] = bcast2(ar[i]);
#pragma unroll
        for (int i = 0; i < 8; i++)
#pragma unroll
            for (int j = 0; j < 4; j++)
                ffma2(acc[i][j], ap[i], bp[j]);
    }
}

__device__ __forceinline__ void zero_acc(unsigned long long (&acc)[8][4]) {
#pragma unroll
    for (int i = 0; i < 8; i++)
#pragma unroll
        for (int j = 0; j < 4; j++) acc[i][j] = 0ULL;
}

// unpack one row of the packed tile to 8 scalars
__device__ __forceinline__ void unpack_row(const unsigned long long (&acc)[8][4],
                                           int i, float (&out)[8]) {
#pragma unroll
    for (int j = 0; j < 4; j++) {
        float2 v = unpack2(acc[i][j]);
        out[2 * j] = v.x; out[2 * j + 1] = v.y;
    }
}

// transpose-stage two float4 (rows r0, r0+64; k-cols k0..k0+3) into S[k][row]
__device__ __forceinline__ void stageT(float* __restrict__ S, int r0, int k0,
                                       float4 a0, float4 a1) {
    S[(k0 + 0) * ZP + r0] = a0.x; S[(k0 + 1) * ZP + r0] = a0.y;
    S[(k0 + 2) * ZP + r0] = a0.z; S[(k0 + 3) * ZP + r0] = a0.w;
    S[(k0 + 0) * ZP + r0 + 64] = a1.x; S[(k0 + 1) * ZP + r0 + 64] = a1.y;
    S[(k0 + 2) * ZP + r0 + 64] = a1.z; S[(k0 + 3) * ZP + r0 + 64] = a1.w;
}

// ---------------- proj GEMM: res = z @ W_in + b_in ----------------
__global__ void __launch_bounds__(256, 2) proj_kernel(
    const float* __restrict__ A, const float* __restrict__ B,
    const float* __restrict__ bias, float* __restrict__ C)
{
    __shared__ float stA[2 * 16 * ZP];
    __shared__ float stB[2 * 16 * ZP];

    const int tid = threadIdx.x;
    const int tx = tid & 15, ty = tid >> 4;
    const int rowBase = blockIdx.y * 128;
    const int colBase = blockIdx.x * 128;
    const int r0 = tid >> 2, k0 = (tid & 3) << 2;
    const int bR = tid >> 5, bC = (tid & 31) << 2;

    const float* aP0 = A + (long)(rowBase + r0) * INDIM;
    const float* aP1 = A + (long)(rowBase + r0 + 64) * INDIM;
    const float* bP  = B + colBase;

    unsigned long long acc[8][4];
    zero_acc(acc);

    float4 a0 = *(const float4*)(aP0 + k0);
    float4 a1 = *(const float4*)(aP1 + k0);
    float4 b0 = *(const float4*)(bP + (long)bR * ENC + bC);
    float4 b1 = *(const float4*)(bP + (long)(bR + 8) * ENC + bC);

    const int NCH = INDIM / 16;   // 48
    for (int s = 0; s < NCH; s++) {
        float* As = stA + (s & 1) * 16 * ZP;
        float* Bs = stB + (s & 1) * 16 * ZP;
        stageT(As, r0, k0, a0, a1);
        *(float4*)&Bs[bR * ZP + bC]       = b0;
        *(float4*)&Bs[(bR + 8) * ZP + bC] = b1;
        __syncthreads();
        if (s + 1 < NCH) {
            int nkt = (s + 1) * 16;
            a0 = *(const float4*)(aP0 + nkt + k0);
            a1 = *(const float4*)(aP1 + nkt + k0);
            b0 = *(const float4*)(bP + (long)(nkt + bR) * ENC + bC);
            b1 = *(const float4*)(bP + (long)(nkt + bR + 8) * ENC + bC);
        }
        mma16p(As, Bs, acc, tx, ty);
    }

    float bb[8];
#pragma unroll
    for (int j = 0; j < 8; j++) bb[j] = bias[colBase + tx * 8 + j];
#pragma unroll
    for (int i = 0; i < 8; i++) {
        float av[8]; unpack_row(acc, i, av);
        long row = rowBase + ty * 8 + i;
        float* cp = C + row * ENC + colBase + tx * 8;
        float4 o0 = make_float4(av[0] + bb[0], av[1] + bb[1],
                                av[2] + bb[2], av[3] + bb[3]);
        float4 o1 = make_float4(av[4] + bb[4], av[5] + bb[5],
                                av[6] + bb[6], av[7] + bb[7]);
        *(float4*)cp = o0; *(float4*)(cp + 4) = o1;
    }
}

// ---------------- fused per-codebook kernel ----------------
// phase 0 (cbIndex>0): res -= prevCb[g_idx] @ prevOutW   (4 col-passes, K=128)
// phase 1: z_e = res @ inW (K=512) -> kept in smem [k][row]; row norms
// phase 2: scores = |c|^2 - 2 * z_e.cb over 8 code tiles; argmin + loss
// All FMA accumulation orders identical to the prior scalar kernels ->
// the z_e chain stays bit-exact (FFMA2 is lane-wise RN fp32).
__global__ void __launch_bounds__(256, 2) fused_kernel(
    float* __restrict__ res,
    const float* __restrict__ prevCb, const float* __restrict__ prevOutW,
    const float* __restrict__ inW, const float* __restrict__ cb,
    float* __restrict__ codesOut, int cbIndex)
{
    extern __shared__ float sm[];
    float* zeS = sm;                              // 128*ZP
    float* stA = sm + 128 * ZP;                   // 2*16*ZP
    float* stB = stA + 2 * 16 * ZP;               // 2*16*ZP
    float* rnS = stB + 2 * 16 * ZP;               // 128
    float* lsS = rnS + 128;                       // 16
    int*   idxS = (int*)(lsS + 16);               // 128

    const int tid = threadIdx.x;
    const int tx = tid & 15, ty = tid >> 4;
    const int rowBase = blockIdx.x * 128;
    const int r0 = tid >> 2, k0 = (tid & 3) << 2;
    const int bR = tid >> 5, bC = (tid & 31) << 2;

    unsigned long long acc[8][4];

    // ================= phase 0: residual update =================
    if (cbIndex > 0) {
        if (tid < 128) idxS[tid] = g_idx[rowBase + tid];
        __syncthreads();
        const float* aP0 = prevCb + (long)idxS[r0] * CDIM;
        const float* aP1 = prevCb + (long)idxS[r0 + 64] * CDIM;

        float4 a0 = *(const float4*)(aP0 + k0);
        float4 a1 = *(const float4*)(aP1 + k0);
        float4 b0 = *(const float4*)(prevOutW + (long)bR * ENC + bC);
        float4 b1 = *(const float4*)(prevOutW + (long)(bR + 8) * ENC + bC);

        for (int s = 0; s < 32; s++) {            // 4 col-passes x 8 k-chunks
            float* As = stA + (s & 1) * 16 * ZP;
            float* Bs = stB + (s & 1) * 16 * ZP;
            stageT(As, r0, k0, a0, a1);
            *(float4*)&Bs[bR * ZP + bC]       = b0;
            *(float4*)&Bs[(bR + 8) * ZP + bC] = b1;
            __syncthreads();
            if (s + 1 < 32) {
                int np = (s + 1) >> 3, nkt = ((s + 1) & 7) << 4;
                a0 = *(const float4*)(aP0 + nkt + k0);
                a1 = *(const float4*)(aP1 + nkt + k0);
                const float* bp = prevOutW + np * 128;
                b0 = *(const float4*)(bp + (long)(nkt + bR) * ENC + bC);
                b1 = *(const float4*)(bp + (long)(nkt + bR + 8) * ENC + bC);
            }
            if ((s & 7) == 0) zero_acc(acc);
            mma16p(As, Bs, acc, tx, ty);
            if ((s & 7) == 7) {
                int colBase = (s >> 3) * 128;
#pragma unroll
                for (int i = 0; i < 8; i++) {
                    float av[8]; unpack_row(acc, i, av);
                    long row = rowBase + ty * 8 + i;
                    float* cp = res + row * ENC + colBase + tx * 8;
                    float4 c0 = *(float4*)cp;
                    float4 c1 = *(float4*)(cp + 4);
                    c0.x -= av[0]; c0.y -= av[1]; c0.z -= av[2]; c0.w -= av[3];
                    c1.x -= av[4]; c1.y -= av[5]; c1.z -= av[6]; c1.w -= av[7];
                    *(float4*)cp = c0; *(float4*)(cp + 4) = c1;
                }
            }
        }
        __syncthreads();   // res update visible block-wide before phase 1
    }

    // ================= phase 1: z_e GEMM (K=512) =================
    {
        const float* aP0 = res + (long)(rowBase + r0) * ENC;
        const float* aP1 = res + (long)(rowBase + r0 + 64) * ENC;

        zero_acc(acc);

        float4 a0 = *(const float4*)(aP0 + k0);
        float4 a1 = *(const float4*)(aP1 + k0);
        float4 b0 = *(const float4*)(inW + (long)bR * CDIM + bC);
        float4 b1 = *(const float4*)(inW + (long)(bR + 8) * CDIM + bC);

        for (int s = 0; s < 32; s++) {            // 32 k-chunks of 16
            float* As = stA + (s & 1) * 16 * ZP;
            float* Bs = stB + (s & 1) * 16 * ZP;
            stageT(As, r0, k0, a0, a1);
            *(float4*)&Bs[bR * ZP + bC]       = b0;
            *(float4*)&Bs[(bR + 8) * ZP + bC] = b1;
            __syncthreads();
            if (s + 1 < 32) {
                int nkt = (s + 1) * 16;
                a0 = *(const float4*)(aP0 + nkt + k0);
                a1 = *(const float4*)(aP1 + nkt + k0);
                b0 = *(const float4*)(inW + (long)(nkt + bR) * CDIM + bC);
                b1 = *(const float4*)(inW + (long)(nkt + bR + 8) * CDIM + bC);
            }
            mma16p(As, Bs, acc, tx, ty);
        }

        // row norms |z_e|^2 + z_e scatter (same order as before)
#pragma unroll
        for (int i = 0; i < 8; i++) {
            float av[8]; unpack_row(acc, i, av);
            float rn = 0.f;
#pragma unroll
            for (int j = 0; j < 8; j++) rn += av[j] * av[j];
#pragma unroll
            for (int off = 8; off; off >>= 1)
                rn += __shfl_down_sync(0xffffffffu, rn, off, 16);
            if (tx == 0) rnS[ty * 8 + i] = rn;
        }
        __syncthreads();   // staging buffers free before z_e transpose-store
#pragma unroll
        for (int i = 0; i < 8; i++) {
            float av[8]; unpack_row(acc, i, av);
#pragma unroll
            for (int j = 0; j < 8; j++)
                zeS[(tx * 8 + j) * ZP + ty * 8 + i] = av[j];
        }
        __syncthreads();
    }

    // ================= phase 2: distance / argmin / loss =================
    float best[8]; int bidx[8];
#pragma unroll
    for (int i = 0; i < 8; i++) { best[i] = FLT_MAX; bidx[i] = 0; }

    float4 b0 = *(const float4*)(cb + (long)r0 * CDIM + k0);
    float4 b1 = *(const float4*)(cb + (long)(r0 + 64) * CDIM + k0);

    for (int s = 0; s < 64; s++) {                // 8 code tiles x 8 k-chunks
        const int kt = (s & 7) << 4;
        float* Bs = ((s & 1) ? stB : stA);        // ping-pong across both buffers
        stageT(Bs, r0, k0, b0, b1);
        __syncthreads();
        if (s + 1 < 64) {
            int nt = (s + 1) >> 3, nkt = ((s + 1) & 7) << 4;
            const float* cp2 = cb + (long)(nt * 128) * CDIM;
            b0 = *(const float4*)(cp2 + (long)r0 * CDIM + nkt + k0);
            b1 = *(const float4*)(cp2 + (long)(r0 + 64) * CDIM + nkt + k0);
        }
        if (kt == 0) zero_acc(acc);
        mma16p(zeS + kt * ZP, Bs, acc, tx, ty);
        if ((s & 7) == 7) {                        // tile complete
            const int t = s >> 3;
            const float* cnp = g_cnorm + cbIndex * NCODE + t * 128 + tx * 8;
            float4 cn0 = *(const float4*)cnp;
            float4 cn1 = *(const float4*)(cnp + 4);
            float cn[8] = {cn0.x, cn0.y, cn0.z, cn0.w, cn1.x, cn1.y, cn1.z, cn1.w};
            const int base = t * 128 + tx * 8;
#pragma unroll
            for (int i = 0; i < 8; i++) {
                float av[8]; unpack_row(acc, i, av);
#pragma unroll
                for (int j = 0; j < 8; j++) {
                    float sc = cn[j] - 2.f * av[j];
                    if (sc < best[i]) { best[i] = sc; bidx[i] = base + j; }
                }
            }
        }
    }

    // cross-thread reduce over tx (width 16), first-index tie-break
    float lossAcc = 0.f;
#pragma unroll
    for (int i = 0; i < 8; i++) {
        float bv = best[i]; int bi = bidx[i];
#pragma unroll
        for (int off = 8; off; off >>= 1) {
            float ov = __shfl_down_sync(0xffffffffu, bv, off, 16);
            int   oi = __shfl_down_sync(0xffffffffu, bi, off, 16);
            if (ov < bv || (ov == bv && oi < bi)) { bv = ov; bi = oi; }
        }
        if (tx == 0) {
            int row = rowBase + ty * 8 + i;
            g_idx[row] = bi;
            codesOut[(long)row * NCB + cbIndex] = (float)bi;
            lossAcc += rnS[ty * 8 + i] + bv;       // = sum_k (z_e - z_q)^2
        }
    }
    if (tx == 0) lsS[ty] = lossAcc;
    __syncthreads();
    if (tid == 0) {
        float sum = 0.f;
        for (int w = 0; w < 16; w++) sum += lsS[w];
        g_losspart[cbIndex * ABLOCKS + blockIdx.x] = sum;
    }
}

// ---------------- deterministic loss finalize (double accumulation) ----------------
__global__ void finalize_kernel(float* __restrict__ out) {
    __shared__ double s[256];
    double v = 0.0;
    for (int i = threadIdx.x; i < NCB * ABLOCKS; i += 256) v += (double)g_losspart[i];
    s[threadIdx.x] = v;
    __syncthreads();
    for (int o = 128; o; o >>= 1) {
        if (threadIdx.x < o) s[threadIdx.x] += s[threadIdx.x + o];
        __syncthreads();
    }
    if (threadIdx.x == 0)
        out[(long)MROWS * NCB] =
            (float)(s[0] * 1.25 / ((double)MROWS * (double)CDIM));
}

// ---------------- launch ----------------
extern "C" void kernel_launch(void* const* d_in, const int* in_sizes, int n_in,
                              void* d_out, int out_size) {
    const float* z     = (const float*)d_in[0];
    const float* W_in  = (const float*)d_in[1];
    const float* b_in  = (const float*)d_in[2];
    const float* cbs   = (const float*)d_in[3];
    const float* in_w  = (const float*)d_in[4];
    const float* out_w = (const float*)d_in[5];
    float* out = (float*)d_out;

    float* res;
    cudaGetSymbolAddress((void**)&res, g_res);

    const int fusedSmem = (128 * ZP + 4 * 16 * ZP + 128 + 16 + 128) * (int)sizeof(float);
    cudaFuncSetAttribute(fused_kernel,
                         cudaFuncAttributeMaxDynamicSharedMemorySize, fusedSmem);

    // |c|^2 for all codebooks
    cnorm_kernel<<<NCB * NCODE / 256, 256>>>(cbs);

    // res = z @ W_in + b_in
    proj_kernel<<<dim3(ENC / 128, MROWS / 128), 256>>>(z, W_in, b_in, res);

    for (int c = 0; c < NCB; c++) {
        fused_kernel<<<ABLOCKS, 256, fusedSmem>>>(
            res,
            c > 0 ? cbs + (long)(c - 1) * NCODE * CDIM : cbs,
            c > 0 ? out_w + (long)(c - 1) * CDIM * ENC : out_w,
            in_w + (long)c * ENC * CDIM,
            cbs + (long)c * NCODE * CDIM,
            out, c);
    }

    finalize_kernel<<<1, 256>>>(out);
}